// round 9
// baseline (speedup 1.0000x reference)
#include <cuda_runtime.h>
#include <stdint.h>
#include <float.h>

#define NROWS   65536
#define DIMS    256
#define NCODES  1024
#define TM      64         // rows per block
#define TC      64         // codes per chunk
#define NCHUNK  (NCODES / TC)
#define MARGIN  1e-3f      // 10 sigma of int8 quant error, 0.11 sigma of code spread
#define MAXC    8          // per-thread candidate cap
#define RSB     272        // int8 row stride bytes -> conflict-free int4 frags

// ---- smem layout (bytes) -------------------------------------------------
#define OFF_ZQ     0                        // 64 x RSB int8              17408
#define OFF_E0     17408                    // 64 x RSB int8              17408
#define OFF_E1     34816                    //                            17408
#define OFF_LIST   52224                    // u64[256][MAXC]             16384
#define OFF_E2     68608                    // f32[1024]                   4096
#define OFF_Z2     72704                    // f32[64]                      256
#define OFF_SZS    72960                    // f32[64]                      256
#define OFF_SES0   73216                    // f32[64]                      256
#define OFF_SES1   73472                    // f32[64]                      256
#define OFF_RMS    73728                    // f32[256][4]                 4096
#define OFF_FMIN   77824                    // i32[64]                      256
#define OFF_BEST   78080                    // u64[64]                      512
#define OFF_IDX    78592                    // i32[64]                      256
#define OFF_ROVF   78848                    // i32[64]                      256
#define OFF_OVFL   79104                    // i32 count + i32[64]          264
#define OFF_RED    79368                    // double[256]                 2048
#define SMEM_BYTES (OFF_RED + 2048)

__device__ float  g_e2[NCODES];
__device__ float  g_se[NCODES];
__device__ char   g_eq[NCODES * DIMS];     // int8-quantized codebook
__device__ double g_loss_accum;

// ---------------------------------------------------------------------------
// prep: per-code e2, int8 quantization of emb, loss zeroing
// ---------------------------------------------------------------------------
__global__ void vq_prep(const float* __restrict__ emb) {
    if (blockIdx.x == 0 && threadIdx.x == 0) g_loss_accum = 0.0;
    int warp = (blockIdx.x * blockDim.x + threadIdx.x) >> 5;
    int lane = threadIdx.x & 31;
    if (warp < NCODES) {
        const float* row = emb + warp * DIMS;
        float s = 0.f, vmax = 0.f;
#pragma unroll
        for (int i = 0; i < DIMS / 32; i++) {
            float v = row[lane + 32 * i];
            s = __fadd_rn(s, __fmul_rn(v, v));
            vmax = fmaxf(vmax, fabsf(v));
        }
#pragma unroll
        for (int o = 16; o > 0; o >>= 1) {
            s    = __fadd_rn(s, __shfl_down_sync(0xffffffffu, s, o));
            vmax = fmaxf(vmax, __shfl_xor_sync(0xffffffffu, vmax, o));
        }
        s = __shfl_sync(0xffffffffu, s, 0);
        if (lane == 0) g_e2[warp] = s;
        float inv = (vmax > 0.f) ? (127.f / vmax) : 0.f;
        if (lane == 0) g_se[warp] = (vmax > 0.f) ? (vmax / 127.f) : 1.f;
        // each lane quantizes dims lane*8 .. lane*8+7
        int q[8];
#pragma unroll
        for (int j = 0; j < 8; j++)
            q[j] = __float2int_rn(row[lane * 8 + j] * inv);
        int2 p;
        p.x = (q[0] & 0xFF) | ((q[1] & 0xFF) << 8) |
              ((q[2] & 0xFF) << 16) | ((q[3] & 0xFF) << 24);
        p.y = (q[4] & 0xFF) | ((q[5] & 0xFF) << 8) |
              ((q[6] & 0xFF) << 16) | ((q[7] & 0xFF) << 24);
        *(int2*)(g_eq + (size_t)warp * DIMS + lane * 8) = p;
    }
}

// stage one 64-code int8 chunk from g_eq + its scales
__device__ __forceinline__ void stage_E(int chunkBase, char* et, float* ses,
                                        int tid) {
#pragma unroll
    for (int i = tid; i < TC * (DIMS / 16); i += 256) {
        int c   = i >> 4;
        int seg = i & 15;
        int4 v = *(const int4*)(g_eq + (size_t)(chunkBase + c) * DIMS + seg * 16);
        *(int4*)(et + (size_t)c * RSB + seg * 16) = v;
    }
    if (tid < TC) ses[tid] = g_se[chunkBase + tid];
}

// canonical exact fp32 distance (R1-proven formula/rounding) + tiebreak pack
__device__ __forceinline__ unsigned long long exact_dist(
    const float* __restrict__ zrow, const float* __restrict__ emb,
    int code, float z2, const float* __restrict__ e2all) {
    const float4* zr = (const float4*)zrow;
    const float4* er = (const float4*)(emb + (size_t)code * DIMS);
    float d0 = 0.f, d1 = 0.f, d2 = 0.f, d3 = 0.f;
#pragma unroll 8
    for (int k4 = 0; k4 < DIMS / 4; k4++) {
        float4 zv = __ldg(&zr[k4]);
        float4 ev = __ldg(&er[k4]);
        d0 = fmaf(zv.x, ev.x, d0);
        d1 = fmaf(zv.y, ev.y, d1);
        d2 = fmaf(zv.z, ev.z, d2);
        d3 = fmaf(zv.w, ev.w, d3);
    }
    float dot  = __fadd_rn(__fadd_rn(d0, d1), __fadd_rn(d2, d3));
    float t    = __fadd_rn(z2, e2all[code]);
    float dist = __fsub_rn(t, __fmul_rn(2.0f, dot));
    return ((unsigned long long)__float_as_uint(dist) << 32) | (unsigned)code;
}

// ---------------------------------------------------------------------------
__global__ void __launch_bounds__(256, 2)
vq_main(const float* __restrict__ z, const float* __restrict__ emb,
        float* __restrict__ out) {
    extern __shared__ char sm[];
    float*  e2all = (float*)(sm + OFF_E2);
    float*  z2sm  = (float*)(sm + OFF_Z2);
    float*  szs   = (float*)(sm + OFF_SZS);
    float*  rmS   = (float*)(sm + OFF_RMS);
    int*    fminI = (int*)(sm + OFF_FMIN);
    unsigned long long* bestU = (unsigned long long*)(sm + OFF_BEST);
    int*    idxs  = (int*)(sm + OFF_IDX);
    int*    rowOvf= (int*)(sm + OFF_ROVF);
    int*    ovfl  = (int*)(sm + OFF_OVFL);
    double* red   = (double*)(sm + OFF_RED);
    unsigned long long* lst =
        (unsigned long long*)(sm + OFF_LIST) + (size_t)threadIdx.x * MAXC;

    const int tid  = threadIdx.x;
    const int lane = tid & 31;
    const int warp = tid >> 5;
    const int wr   = warp >> 2;          // 0-1: 32-row group
    const int wc   = warp & 3;           // 0-3: 16-code group
    const int tr   = lane >> 2;          // 0-7
    const int tc   = lane & 3;           // 0-3
    const int rowBase = blockIdx.x * TM;
    const float* zblk = z + (size_t)rowBase * DIMS;

    if (tid < TM) {
        fminI[tid]  = 0x7f800000;
        bestU[tid]  = ~0ull;
        rowOvf[tid] = 0;
    }
    if (tid == 0) ovfl[0] = 0;

    // ---- phase 1: per-row z2 + max (thread = row) ----
    if (tid < TM) {
        const float4* zr = (const float4*)(zblk + (size_t)tid * DIMS);
        float s = 0.f, vmax = 0.f;
        for (int k4 = 0; k4 < DIMS / 4; k4++) {
            float4 v = __ldg(&zr[k4]);
            s = __fadd_rn(s, __fmul_rn(v.x, v.x));
            s = __fadd_rn(s, __fmul_rn(v.y, v.y));
            s = __fadd_rn(s, __fmul_rn(v.z, v.z));
            s = __fadd_rn(s, __fmul_rn(v.w, v.w));
            vmax = fmaxf(vmax, fmaxf(fmaxf(fabsf(v.x), fabsf(v.y)),
                                     fmaxf(fabsf(v.z), fabsf(v.w))));
        }
        z2sm[tid] = s;
        szs[tid]  = (vmax > 0.f) ? (vmax / 127.f) : 0.f;
    }
    for (int i = tid; i < NCODES; i += 256) e2all[i] = g_e2[i];
    __syncthreads();

    // ---- phase 2: quantize z tile to int8 smem ----
    for (int i = tid; i < TM * (DIMS / 16); i += 256) {
        int r   = i >> 4;
        int seg = i & 15;
        float sv  = szs[r];
        float inv = (sv > 0.f) ? (1.f / sv) : 0.f;
        const float4* zr = (const float4*)(zblk + (size_t)r * DIMS + seg * 16);
        int4 pk;
        int* pw = (int*)&pk;
#pragma unroll
        for (int q4 = 0; q4 < 4; q4++) {
            float4 v = __ldg(&zr[q4]);
            int a = __float2int_rn(v.x * inv) & 0xFF;
            int b = __float2int_rn(v.y * inv) & 0xFF;
            int c = __float2int_rn(v.z * inv) & 0xFF;
            int d = __float2int_rn(v.w * inv) & 0xFF;
            pw[q4] = a | (b << 8) | (c << 16) | (d << 24);
        }
        *(int4*)(sm + OFF_ZQ + (size_t)r * RSB + seg * 16) = pk;
    }
    stage_E(0, sm + OFF_E0, (float*)(sm + OFF_SES0), tid);
    __syncthreads();

    const char* zb = sm + OFF_ZQ + (size_t)(wr * 32 + tr) * RSB;  // rows +8i
    const int   cb = wc * 16 + tc;                                 // codes +4j
    float z2sl[4], szsl[4];
#pragma unroll
    for (int i = 0; i < 4; i++) {
        z2sl[i] = z2sm[wr * 32 + tr + 8 * i];
        szsl[i] = szs[wr * 32 + tr + 8 * i];
    }

    float rm[4];
#pragma unroll
    for (int i = 0; i < 4; i++) rm[i] = FLT_MAX;
    int cn = 0;
    bool ovfflag = false;

    auto insert_cand = [&](float da, int tag) {
        if (cn == MAXC) {
            float* rs = rmS + tid * 4;
#pragma unroll
            for (int i = 0; i < 4; i++) rs[i] = rm[i];
            int w = 0;
            for (int t = 0; t < MAXC; t++) {
                unsigned long long e = lst[t];
                float v = __uint_as_float((unsigned)(e >> 32));
                int s = ((int)(e & 0xFFFu)) >> 10;
                if (v <= rs[s] + MARGIN) lst[w++] = e;
            }
            cn = w;
        }
        if (cn < MAXC)
            lst[cn++] = ((unsigned long long)__float_as_uint(da) << 32) | (unsigned)tag;
        else
            ovfflag = true;
    };
#define TRACK(da, slot, rmv, code)                                   \
    { float _d = (da);                                               \
      if (_d < rmv) rmv = _d;                                        \
      if (_d <= rmv + MARGIN) insert_cand(_d, ((slot) << 10) | (code)); }

    // ================= chunk loop: dp4a GEMM + candidate tracking ==========
    for (int c = 0; c < NCHUNK; c++) {
        const int bb = c & 1;
        const char*  eb  = sm + (bb ? OFF_E1 : OFF_E0) + (size_t)cb * RSB;
        const float* ses = (const float*)(sm + (bb ? OFF_SES1 : OFF_SES0));
        if (c + 1 < NCHUNK)
            stage_E((c + 1) * TC, sm + (bb ? OFF_E0 : OFF_E1),
                    (float*)(sm + (bb ? OFF_SES0 : OFF_SES1)), tid);

        int acc[4][4];
#pragma unroll
        for (int i = 0; i < 4; i++)
#pragma unroll
            for (int j = 0; j < 4; j++) acc[i][j] = 0;

#pragma unroll 4
        for (int kg = 0; kg < DIMS / 16; kg++) {   // 16 dims per int4
            int4 zf[4], ef[4];
#pragma unroll
            for (int i = 0; i < 4; i++)
                zf[i] = *(const int4*)(zb + (size_t)i * 8 * RSB + kg * 16);
#pragma unroll
            for (int j = 0; j < 4; j++)
                ef[j] = *(const int4*)(eb + (size_t)j * 4 * RSB + kg * 16);
#pragma unroll
            for (int i = 0; i < 4; i++)
#pragma unroll
                for (int j = 0; j < 4; j++) {
                    acc[i][j] = __dp4a(zf[i].x, ef[j].x, acc[i][j]);
                    acc[i][j] = __dp4a(zf[i].y, ef[j].y, acc[i][j]);
                    acc[i][j] = __dp4a(zf[i].z, ef[j].z, acc[i][j]);
                    acc[i][j] = __dp4a(zf[i].w, ef[j].w, acc[i][j]);
                }
        }

        const int chunkBase = c * TC;
#pragma unroll
        for (int i = 0; i < 4; i++) {
            float z2e = z2sl[i];
            float szi = szsl[i];
#pragma unroll
            for (int j = 0; j < 4; j++) {
                int lc   = cb + 4 * j;
                int code = chunkBase + lc;
                float ns = -2.0f * szi * ses[lc];
                float da = fmaf(ns, (float)acc[i][j], z2e + e2all[code]);
                TRACK(da, i, rm[i], code);
            }
        }
        __syncthreads();
    }

    // ---- merge per-row approx minima ----
#pragma unroll
    for (int i = 0; i < 4; i++)
        atomicMin(&fminI[wr * 32 + tr + 8 * i], __float_as_int(rm[i]));
    if (ovfflag)
#pragma unroll
        for (int i = 0; i < 4; i++) rowOvf[wr * 32 + tr + 8 * i] = 1;
    __syncthreads();

    // ---- exact rescore of surviving candidates (canonical formula) ----
    for (int t = 0; t < cn; t++) {
        unsigned long long e = lst[t];
        float v  = __uint_as_float((unsigned)(e >> 32));
        int tag  = (int)(e & 0xFFFu);
        int s    = tag >> 10;
        int code = tag & 1023;
        int row  = wr * 32 + tr + 8 * s;
        if (v <= __int_as_float(fminI[row]) + MARGIN) {
            unsigned long long p =
                exact_dist(zblk + (size_t)row * DIMS, emb, code, z2sm[row], e2all);
            atomicMin(&bestU[row], p);
        }
    }
    __syncthreads();

    // ---- overflow rows: full exact scan (safety net, ~never taken) ----
    if (tid < TM && rowOvf[tid]) {
        int p = atomicAdd(&ovfl[0], 1);
        ovfl[1 + p] = tid;
    }
    __syncthreads();
    int novf = ovfl[0];
    for (int f = 0; f < novf; f++) {
        int row = ovfl[1 + f];
        float z2r = z2sm[row];
        for (int code = tid; code < NCODES; code += 256) {
            unsigned long long p =
                exact_dist(zblk + (size_t)row * DIMS, emb, code, z2r, e2all);
            atomicMin(&bestU[row], p);
        }
    }
    if (novf) __syncthreads();

    if (tid < TM) idxs[tid] = (int)(bestU[tid] & 0xffffffffull);
    __syncthreads();

    // ================= epilogue: gather / STE / loss ======================
    double lsum = 0.0;
    float* outblk = out + (size_t)rowBase * DIMS;
#pragma unroll 4
    for (int i = tid; i < TM * (DIMS / 4); i += 256) {
        int r  = i >> 6;
        int k4 = i & 63;
        float4 zv = __ldg(&((const float4*)zblk)[(size_t)r * (DIMS / 4) + k4]);
        float4 qv = __ldg(&((const float4*)(emb + (size_t)idxs[r] * DIMS))[k4]);
        float4 ov; float d;
        d = __fsub_rn(qv.x, zv.x); ov.x = __fadd_rn(zv.x, d); lsum += (double)__fmul_rn(d, d);
        d = __fsub_rn(qv.y, zv.y); ov.y = __fadd_rn(zv.y, d); lsum += (double)__fmul_rn(d, d);
        d = __fsub_rn(qv.z, zv.z); ov.z = __fadd_rn(zv.z, d); lsum += (double)__fmul_rn(d, d);
        d = __fsub_rn(qv.w, zv.w); ov.w = __fadd_rn(zv.w, d); lsum += (double)__fmul_rn(d, d);
        ((float4*)outblk)[i] = ov;
    }
    red[tid] = lsum;
    __syncthreads();
    for (int s = 128; s > 0; s >>= 1) {
        if (tid < s) red[tid] += red[tid + s];
        __syncthreads();
    }
    if (tid == 0) atomicAdd(&g_loss_accum, red[0]);
}

// ---------------------------------------------------------------------------
__global__ void vq_finalize(float* __restrict__ out, int out_size) {
    double mean = g_loss_accum / (double)((size_t)NROWS * DIMS);
    float loss = (float)(0.5 * mean);
    out[out_size - 2] = loss;   // commitment_loss
    out[out_size - 1] = loss;   // emb_loss
}

// ---------------------------------------------------------------------------
extern "C" void kernel_launch(void* const* d_in, const int* in_sizes, int n_in,
                              void* d_out, int out_size) {
    const float* z   = (const float*)d_in[0];
    const float* emb = (const float*)d_in[1];
    if (n_in >= 2 && in_sizes[0] == NCODES * DIMS && in_sizes[1] == NROWS * DIMS) {
        emb = (const float*)d_in[0];
        z   = (const float*)d_in[1];
    }
    float* out = (float*)d_out;

    vq_prep<<<(NCODES * 32 + 255) / 256, 256>>>(emb);

    cudaFuncSetAttribute(vq_main, cudaFuncAttributeMaxDynamicSharedMemorySize,
                         SMEM_BYTES);
    vq_main<<<NROWS / TM, 256, SMEM_BYTES>>>(z, emb, out);

    vq_finalize<<<1, 1>>>(out, out_size);
}